// round 2
// baseline (speedup 1.0000x reference)
#include <cuda_runtime.h>
#include <math.h>

// ---------------------------------------------------------------------------
// Scratch (device globals; allocation-free per harness rules). Total ~42 MB.
// ---------------------------------------------------------------------------
__device__ float g_W[1572864];        // combined weights: up to 12288 x 128 (6 MB)
__device__ float g_act1[4194304];     // (512,16,16,32) NHWC
__device__ float g_act2[2097152];     // (512,8,8,64)   NHWC
__device__ float g_act3[1048576];     // (512,4,4,128)  NHWC
__device__ float g_act4[262144];      // (512,2,2,128)  NHWC
__device__ float g_part[1048576];     // split-K partials layer 4 (4 x 2048 x 128)
__device__ float g_bnS1[64],  g_bnT1[64];
__device__ float g_bnS2[128], g_bnT2[128];
__device__ float g_bnS3[128], g_bnT3[128];

// ---------------------------------------------------------------------------
// Quadratic B-spline bases (grid_size=3, order=2, range [-1,1]) -> 5 bases.
// Exactly mirrors the reference Cox-de Boor recursion (half-open intervals).
// ---------------------------------------------------------------------------
__device__ __forceinline__ void spline5(float x, float* bo) {
    float g[8];
#pragma unroll
    for (int i = 0; i < 8; i++) g[i] = (float)(i - 2) * (2.0f / 3.0f) - 1.0f;
    float b0[7];
#pragma unroll
    for (int j = 0; j < 7; j++) b0[j] = (x >= g[j] && x < g[j + 1]) ? 1.0f : 0.0f;
    float b1[6];
#pragma unroll
    for (int j = 0; j < 6; j++)
        b1[j] = (x - g[j]) * (1.0f / (g[j + 1] - g[j])) * b0[j]
              + (g[j + 2] - x) * (1.0f / (g[j + 2] - g[j + 1])) * b0[j + 1];
#pragma unroll
    for (int j = 0; j < 5; j++)
        bo[j] = (x - g[j]) * (1.0f / (g[j + 2] - g[j])) * b1[j]
              + (g[j + 3] - x) * (1.0f / (g[j + 3] - g[j + 1])) * b1[j + 1];
}

// ---------------------------------------------------------------------------
// Combined weight build: W[k][o], k = f*6 + t; t==0 -> base weight (relu path),
// t=1..5 -> spline weight * scaler. Row-major k, N-contiguous o.
// ---------------------------------------------------------------------------
__global__ void build_w_kernel(const float* __restrict__ bw,
                               const float* __restrict__ sw,
                               const float* __restrict__ sc,
                               float* __restrict__ W, int F, int O) {
    int idx = blockIdx.x * blockDim.x + threadIdx.x;
    int total = 6 * F * O;
    if (idx >= total) return;
    int o = idx % O;
    int k = idx / O;
    int f = k / 6;
    int t = k % 6;
    float val;
    if (t == 0) val = bw[o * F + f];
    else        val = sw[(o * F + f) * 5 + (t - 1)] * sc[o * F + f];
    W[idx] = val;
}

// ---------------------------------------------------------------------------
// Fused KAN-conv GEMM: C[M,O] = Aexp[M,6F] * W[6F,O], where Aexp row m is
// [relu(f0), b0..b4(f0), relu(f1), ...] computed ON THE FLY from the source
// activation tensor (unfold 4x4 stride2 pad1, optional preceding-BN affine
// applied only to in-bounds values; pads stay exactly 0 as in the reference).
//
// grid.z = split over the feature range (deterministic split-K): block z
// covers features [z*fCount, (z+1)*fCount) and writes C + z*M*O.
//
// hs = log2(Hout). 256 threads. BK = 6*BF k-values per chunk.
// ---------------------------------------------------------------------------
template <int BM, int BN, int BF, int TM, int TN>
__global__ __launch_bounds__(256)
void kan_gemm_kernel(const float* __restrict__ src,
                     const float* __restrict__ Wc,
                     float* __restrict__ C,
                     const float* __restrict__ bns,
                     const float* __restrict__ bnt,
                     int M, int O, int Cin, int Hin, int hs, int nchw,
                     int fCount) {
    constexpr int BK = 6 * BF;
    __shared__ float As[BK][BM];
    __shared__ float Bs[BK][BN];

    const int z = blockIdx.z;
    const int fBase = z * fCount;
    const int row0 = blockIdx.x * BM;
    const int col0 = blockIdx.y * BN;
    float* Cz = C + z * M * O;

    const int tid = threadIdx.x;
    constexpr int NT = BN / TN;           // threads along N
    const int tx = tid % NT;
    const int ty = tid / NT;

    float acc[TM][TN];
#pragma unroll
    for (int i = 0; i < TM; i++)
#pragma unroll
        for (int jj = 0; jj < TN; jj++) acc[i][jj] = 0.0f;

    const int Hout = 1 << hs;
    const int hwMask = (Hout * Hout) - 1;
    const int hwShift = 2 * hs;

    for (int fc = 0; fc < fCount; fc += BF) {
        // ---- A: gather raw features, expand to 6 bases, store to smem ----
#pragma unroll
        for (int l = tid; l < BM * BF; l += 256) {
            const int mLocal = l % BM;
            const int fl = l / BM;
            const int m = row0 + mLocal;
            const int f = fBase + fc + fl;
            const int p = m & hwMask;
            const int b = m >> hwShift;
            const int ho = p >> hs, wo = p & (Hout - 1);
            const int c = f >> 4;
            const int r = f & 15;
            const int ih = 2 * ho + (r >> 2) - 1;
            const int iw = 2 * wo + (r & 3) - 1;
            float v = 0.0f;
            if ((unsigned)ih < (unsigned)Hin && (unsigned)iw < (unsigned)Hin) {
                int off = nchw
                    ? (((b * Cin + c) * Hin + ih) * Hin + iw)
                    : (((b * Hin + ih) * Hin + iw) * Cin + c);
                v = src[off];
                if (bns) v = fmaf(v, bns[c], bnt[c]);  // prev-layer BN (not on pads)
            }
            As[fl * 6 + 0][mLocal] = fmaxf(v, 0.0f);
            float bb[5];
            spline5(v, bb);
#pragma unroll
            for (int t = 0; t < 5; t++) As[fl * 6 + 1 + t][mLocal] = bb[t];
        }
        // ---- B: combined weights ----
        constexpr int BN4 = BN / 4;
#pragma unroll
        for (int l = tid; l < BK * BN4; l += 256) {
            const int kr = l / BN4;
            const int cn = (l % BN4) * 4;
            const int kg = (fBase + fc) * 6 + kr;
            *(float4*)&Bs[kr][cn] = *(const float4*)&Wc[kg * O + col0 + cn];
        }
        __syncthreads();

#pragma unroll
        for (int k = 0; k < BK; k++) {
            float a[TM], bb[TN];
#pragma unroll
            for (int i = 0; i < TM; i++) a[i] = As[k][ty * TM + i];
#pragma unroll
            for (int jj = 0; jj < TN; jj++) bb[jj] = Bs[k][tx * TN + jj];
#pragma unroll
            for (int i = 0; i < TM; i++)
#pragma unroll
                for (int jj = 0; jj < TN; jj++)
                    acc[i][jj] = fmaf(a[i], bb[jj], acc[i][jj]);
        }
        __syncthreads();
    }

#pragma unroll
    for (int i = 0; i < TM; i++) {
        int rowoff = (row0 + ty * TM + i) * O + col0 + tx * TN;
#pragma unroll
        for (int jj = 0; jj < TN; jj++) Cz[rowoff + jj] = acc[i][jj];
    }
}

// ---------------------------------------------------------------------------
// Split-K reduce (deterministic, no atomics)
// ---------------------------------------------------------------------------
__global__ void reduce_splitk_kernel(const float* __restrict__ part,
                                     float* __restrict__ out, int MN, int S) {
    int idx = blockIdx.x * blockDim.x + threadIdx.x;
    if (idx >= MN) return;
    float a = 0.0f;
    for (int s = 0; s < S; s++) a += part[s * MN + idx];
    out[idx] = a;
}

// ---------------------------------------------------------------------------
// BN statistics: per-channel mean/var over n elements (NHWC, stride C),
// producing the fused affine: y = x*s + t. Double accum => deterministic+exact.
// ---------------------------------------------------------------------------
__global__ void bnstats_kernel(const float* __restrict__ act,
                               const float* __restrict__ gamma,
                               const float* __restrict__ beta,
                               float* __restrict__ s_out,
                               float* __restrict__ t_out, int n, int C) {
    int c = blockIdx.x;
    double sum = 0.0, sum2 = 0.0;
    for (int e = threadIdx.x; e < n; e += blockDim.x) {
        float v = act[e * C + c];
        sum += v;
        sum2 += (double)v * v;
    }
    __shared__ double shs[256];
    __shared__ double sh2[256];
    shs[threadIdx.x] = sum;
    sh2[threadIdx.x] = sum2;
    __syncthreads();
    for (int o = 128; o > 0; o >>= 1) {
        if (threadIdx.x < o) {
            shs[threadIdx.x] += shs[threadIdx.x + o];
            sh2[threadIdx.x] += sh2[threadIdx.x + o];
        }
        __syncthreads();
    }
    if (threadIdx.x == 0) {
        double mean = shs[0] / n;
        double var = sh2[0] / n - mean * mean;
        double sv = (double)gamma[c] * rsqrt(var + 1e-5);
        s_out[c] = (float)sv;
        t_out[c] = (float)((double)beta[c] - mean * sv);
    }
}

// ---------------------------------------------------------------------------
// Head: BN3 affine + avgpool(2x2) + fc(128->1) + sigmoid. One block per batch.
// ---------------------------------------------------------------------------
__global__ void head_kernel(const float* __restrict__ act4,
                            const float* __restrict__ s,
                            const float* __restrict__ t,
                            const float* __restrict__ fcw,
                            const float* __restrict__ fcb,
                            float* __restrict__ out) {
    int b = blockIdx.x;
    int c = threadIdx.x;  // 128 threads
    const float* p = act4 + b * 4 * 128;
    float mval = 0.25f * (p[c] + p[128 + c] + p[256 + c] + p[384 + c]);
    float v = (s[c] * mval + t[c]) * fcw[c];
    __shared__ float sh[128];
    sh[c] = v;
    __syncthreads();
    for (int o = 64; o > 0; o >>= 1) {
        if (c < o) sh[c] += sh[c + o];
        __syncthreads();
    }
    if (c == 0) {
        float zv = sh[0] + fcb[0];
        out[b] = 1.0f / (1.0f + expf(-zv));
    }
}

// ---------------------------------------------------------------------------
// Launch
// ---------------------------------------------------------------------------
extern "C" void kernel_launch(void* const* d_in, const int* in_sizes, int n_in,
                              void* d_out, int out_size) {
    const float* x   = (const float*)d_in[0];
    const float* bw1 = (const float*)d_in[1];
    const float* sw1 = (const float*)d_in[2];
    const float* sc1 = (const float*)d_in[3];
    const float* bw2 = (const float*)d_in[4];
    const float* sw2 = (const float*)d_in[5];
    const float* sc2 = (const float*)d_in[6];
    const float* bw3 = (const float*)d_in[7];
    const float* sw3 = (const float*)d_in[8];
    const float* sc3 = (const float*)d_in[9];
    const float* bw4 = (const float*)d_in[10];
    const float* sw4 = (const float*)d_in[11];
    const float* sc4 = (const float*)d_in[12];
    const float* g1  = (const float*)d_in[13];
    const float* b1  = (const float*)d_in[14];
    const float* g2  = (const float*)d_in[15];
    const float* b2  = (const float*)d_in[16];
    const float* g3  = (const float*)d_in[17];
    const float* b3  = (const float*)d_in[18];
    const float* fcw = (const float*)d_in[19];
    const float* fcb = (const float*)d_in[20];
    float* out = (float*)d_out;

    float *W, *act1, *act2, *act3, *act4, *part;
    float *s1, *t1, *s2, *t2, *s3, *t3;
    cudaGetSymbolAddress((void**)&W, g_W);
    cudaGetSymbolAddress((void**)&act1, g_act1);
    cudaGetSymbolAddress((void**)&act2, g_act2);
    cudaGetSymbolAddress((void**)&act3, g_act3);
    cudaGetSymbolAddress((void**)&act4, g_act4);
    cudaGetSymbolAddress((void**)&part, g_part);
    cudaGetSymbolAddress((void**)&s1, g_bnS1);
    cudaGetSymbolAddress((void**)&t1, g_bnT1);
    cudaGetSymbolAddress((void**)&s2, g_bnS2);
    cudaGetSymbolAddress((void**)&t2, g_bnT2);
    cudaGetSymbolAddress((void**)&s3, g_bnS3);
    cudaGetSymbolAddress((void**)&t3, g_bnT3);

    // ---- Layer 1: (512,3,32,32) NCHW -> (512,16,16,32) NHWC -----------------
    {
        const int F = 48, O = 32, M = 512 * 16 * 16;
        build_w_kernel<<<(6 * F * O + 255) / 256, 256>>>(bw1, sw1, sc1, W, F, O);
        kan_gemm_kernel<128, 32, 8, 8, 2><<<dim3(M / 128, 1, 1), 256>>>(
            x, W, act1, nullptr, nullptr, M, O, 3, 32, 4, 1, F);
    }
    // ---- Layer 2: -> (512,8,8,64), then BN1 stats ---------------------------
    {
        const int F = 512, O = 64, M = 512 * 8 * 8;
        build_w_kernel<<<(6 * F * O + 255) / 256, 256>>>(bw2, sw2, sc2, W, F, O);
        kan_gemm_kernel<128, 64, 8, 8, 4><<<dim3(M / 128, 1, 1), 256>>>(
            act1, W, act2, nullptr, nullptr, M, O, 32, 16, 3, 0, F);
        bnstats_kernel<<<64, 256>>>(act2, g1, b1, s1, t1, 512 * 64, 64);
    }
    // ---- Layer 3: BN1 fused in gather -> (512,4,4,128), BN2 stats -----------
    {
        const int F = 1024, O = 128, M = 512 * 4 * 4;
        build_w_kernel<<<(6 * F * O + 255) / 256, 256>>>(bw3, sw3, sc3, W, F, O);
        kan_gemm_kernel<64, 64, 8, 4, 4><<<dim3(M / 64, O / 64, 1), 256>>>(
            act2, W, act3, s1, t1, M, O, 64, 8, 2, 0, F);
        bnstats_kernel<<<128, 256>>>(act3, g2, b2, s2, t2, 512 * 16, 128);
    }
    // ---- Layer 4: BN2 fused -> (512,2,2,128) via split-K(4), BN3 stats ------
    {
        const int F = 2048, O = 128, M = 512 * 2 * 2;
        const int SPLIT = 4;
        build_w_kernel<<<(6 * F * O + 255) / 256, 256>>>(bw4, sw4, sc4, W, F, O);
        kan_gemm_kernel<64, 64, 8, 4, 4><<<dim3(M / 64, O / 64, SPLIT), 256>>>(
            act3, W, part, s2, t2, M, O, 128, 4, 1, 0, F / SPLIT);
        reduce_splitk_kernel<<<(M * O + 255) / 256, 256>>>(part, act4, M * O, SPLIT);
        bnstats_kernel<<<128, 256>>>(act4, g3, b3, s3, t3, 512 * 4, 128);
    }
    // ---- Head: BN3 + avgpool + fc + sigmoid ---------------------------------
    head_kernel<<<512, 128>>>(act4, s3, t3, fcw, fcb, out);
}

// round 3
// speedup vs baseline: 1.0801x; 1.0801x over previous
#include <cuda_runtime.h>
#include <math.h>

// ---------------------------------------------------------------------------
// Scratch (device globals; allocation-free). ~50 MB total.
// ---------------------------------------------------------------------------
__device__ float g_W[1572864];        // combined weights: up to 12288 x 128
__device__ float g_act1[4194304];     // (512,16,16,32) NHWC
__device__ float g_act2[2097152];     // (512,8,8,64)   NHWC
__device__ float g_act3[1048576];     // (512,4,4,128)  NHWC
__device__ float g_act4[262144];      // (512,2,2,128)  NHWC
__device__ float g_part[4194304];     // split-K partials (max: L2, 2 x 32768 x 64)
__device__ float g_bnS1[64],  g_bnT1[64];
__device__ float g_bnS2[128], g_bnT2[128];
__device__ float g_bnS3[128], g_bnT3[128];

// ---------------------------------------------------------------------------
// Quadratic B-spline bases (grid_size=3, order=2, range [-1,1]) -> 5 bases.
// Exactly mirrors the reference Cox-de Boor recursion (half-open intervals).
// ---------------------------------------------------------------------------
__device__ __forceinline__ void spline5(float x, float* bo) {
    float g[8];
#pragma unroll
    for (int i = 0; i < 8; i++) g[i] = (float)(i - 2) * (2.0f / 3.0f) - 1.0f;
    float b0[7];
#pragma unroll
    for (int j = 0; j < 7; j++) b0[j] = (x >= g[j] && x < g[j + 1]) ? 1.0f : 0.0f;
    float b1[6];
#pragma unroll
    for (int j = 0; j < 6; j++)
        b1[j] = (x - g[j]) * (1.0f / (g[j + 1] - g[j])) * b0[j]
              + (g[j + 2] - x) * (1.0f / (g[j + 2] - g[j + 1])) * b0[j + 1];
#pragma unroll
    for (int j = 0; j < 5; j++)
        bo[j] = (x - g[j]) * (1.0f / (g[j + 2] - g[j])) * b1[j]
              + (g[j + 3] - x) * (1.0f / (g[j + 3] - g[j + 1])) * b1[j + 1];
}

// ---------------------------------------------------------------------------
// Combined weight build: W[k][o], k = f*6 + t; t==0 -> base weight,
// t=1..5 -> spline weight * scaler.
// ---------------------------------------------------------------------------
__global__ void build_w_kernel(const float* __restrict__ bw,
                               const float* __restrict__ sw,
                               const float* __restrict__ sc,
                               float* __restrict__ W, int F, int O) {
    int idx = blockIdx.x * blockDim.x + threadIdx.x;
    int total = 6 * F * O;
    if (idx >= total) return;
    int o = idx % O;
    int k = idx / O;
    int f = k / 6;
    int t = k % 6;
    float val;
    if (t == 0) val = bw[o * F + f];
    else        val = sw[(o * F + f) * 5 + (t - 1)] * sc[o * F + f];
    W[idx] = val;
}

// ---------------------------------------------------------------------------
// Fused KAN-conv GEMM. A tile computed on the fly (unfold + optional BN affine
// + relu/spline expansion); inner loop uses float4 LDS. TM=8, TN=4 fixed.
// grid.z splits the feature range (deterministic split-K, no expansion dup).
// ---------------------------------------------------------------------------
template <int BM, int BN, int BF>
__global__ __launch_bounds__((BM / 8) * (BN / 4))
void kan_gemm_kernel(const float* __restrict__ src,
                     const float* __restrict__ Wc,
                     float* __restrict__ C,
                     const float* __restrict__ bns,
                     const float* __restrict__ bnt,
                     int M, int O, int Cin, int Hin, int hs, int nchw,
                     int fCount) {
    constexpr int BK = 6 * BF;
    constexpr int TM = 8, TN = 4;
    constexpr int NT = BN / TN;
    constexpr int THREADS = (BM / TM) * NT;
    __shared__ __align__(16) float As[BK][BM];
    __shared__ __align__(16) float Bs[BK][BN];

    const int z = blockIdx.z;
    const int fBase = z * fCount;
    const int row0 = blockIdx.x * BM;
    const int col0 = blockIdx.y * BN;
    float* Cz = C + z * M * O;

    const int tid = threadIdx.x;
    const int tx = tid % NT;
    const int ty = tid / NT;

    float acc[TM][TN];
#pragma unroll
    for (int i = 0; i < TM; i++)
#pragma unroll
        for (int jj = 0; jj < TN; jj++) acc[i][jj] = 0.0f;

    const int Hout = 1 << hs;
    const int hwMask = (Hout * Hout) - 1;
    const int hwShift = 2 * hs;

    for (int fc = 0; fc < fCount; fc += BF) {
        // ---- A: gather raw features, expand to 6 bases, store to smem ----
#pragma unroll
        for (int l = tid; l < BM * BF; l += THREADS) {
            const int mLocal = l % BM;
            const int fl = l / BM;
            const int m = row0 + mLocal;
            const int f = fBase + fc + fl;
            const int p = m & hwMask;
            const int b = m >> hwShift;
            const int ho = p >> hs, wo = p & (Hout - 1);
            const int c = f >> 4;
            const int r = f & 15;
            const int ih = 2 * ho + (r >> 2) - 1;
            const int iw = 2 * wo + (r & 3) - 1;
            float v = 0.0f;
            if ((unsigned)ih < (unsigned)Hin && (unsigned)iw < (unsigned)Hin) {
                int off = nchw
                    ? (((b * Cin + c) * Hin + ih) * Hin + iw)
                    : (((b * Hin + ih) * Hin + iw) * Cin + c);
                v = src[off];
                if (bns) v = fmaf(v, bns[c], bnt[c]);  // prev BN (not on pads)
            }
            As[fl * 6 + 0][mLocal] = fmaxf(v, 0.0f);
            float bb[5];
            spline5(v, bb);
#pragma unroll
            for (int t = 0; t < 5; t++) As[fl * 6 + 1 + t][mLocal] = bb[t];
        }
        // ---- B: combined weights (float4 global loads) ----
        constexpr int BN4 = BN / 4;
#pragma unroll
        for (int l = tid; l < BK * BN4; l += THREADS) {
            const int kr = l / BN4;
            const int cn = (l % BN4) * 4;
            const int kg = (fBase + fc) * 6 + kr;
            *(float4*)&Bs[kr][cn] = *(const float4*)&Wc[kg * O + col0 + cn];
        }
        __syncthreads();

        // ---- compute: 3x LDS.128 + 32 FMA per k ----
#pragma unroll
        for (int k = 0; k < BK; k++) {
            float4 a0 = *(const float4*)&As[k][ty * TM];
            float4 a1 = *(const float4*)&As[k][ty * TM + 4];
            float4 b0 = *(const float4*)&Bs[k][tx * TN];
            const float av[8] = {a0.x, a0.y, a0.z, a0.w, a1.x, a1.y, a1.z, a1.w};
            const float bv[4] = {b0.x, b0.y, b0.z, b0.w};
#pragma unroll
            for (int i = 0; i < TM; i++)
#pragma unroll
                for (int jj = 0; jj < TN; jj++)
                    acc[i][jj] = fmaf(av[i], bv[jj], acc[i][jj]);
        }
        __syncthreads();
    }

#pragma unroll
    for (int i = 0; i < TM; i++) {
        int rowoff = (row0 + ty * TM + i) * O + col0 + tx * TN;
        float4 o4 = make_float4(acc[i][0], acc[i][1], acc[i][2], acc[i][3]);
        *(float4*)&Cz[rowoff] = o4;
    }
}

// ---------------------------------------------------------------------------
// Split-K reduce (deterministic, no atomics)
// ---------------------------------------------------------------------------
__global__ void reduce_splitk_kernel(const float* __restrict__ part,
                                     float* __restrict__ out, int MN, int S) {
    int idx = blockIdx.x * blockDim.x + threadIdx.x;
    if (idx >= MN) return;
    float a = 0.0f;
    for (int s = 0; s < S; s++) a += part[s * MN + idx];
    out[idx] = a;
}

// ---------------------------------------------------------------------------
// BN statistics -> fused affine y = x*s + t (double accum, deterministic).
// ---------------------------------------------------------------------------
__global__ void bnstats_kernel(const float* __restrict__ act,
                               const float* __restrict__ gamma,
                               const float* __restrict__ beta,
                               float* __restrict__ s_out,
                               float* __restrict__ t_out, int n, int C) {
    int c = blockIdx.x;
    double sum = 0.0, sum2 = 0.0;
    for (int e = threadIdx.x; e < n; e += blockDim.x) {
        float v = act[e * C + c];
        sum += v;
        sum2 += (double)v * v;
    }
    __shared__ double shs[256];
    __shared__ double sh2[256];
    shs[threadIdx.x] = sum;
    sh2[threadIdx.x] = sum2;
    __syncthreads();
    for (int o = 128; o > 0; o >>= 1) {
        if (threadIdx.x < o) {
            shs[threadIdx.x] += shs[threadIdx.x + o];
            sh2[threadIdx.x] += sh2[threadIdx.x + o];
        }
        __syncthreads();
    }
    if (threadIdx.x == 0) {
        double mean = shs[0] / n;
        double var = sh2[0] / n - mean * mean;
        double sv = (double)gamma[c] * rsqrt(var + 1e-5);
        s_out[c] = (float)sv;
        t_out[c] = (float)((double)beta[c] - mean * sv);
    }
}

// ---------------------------------------------------------------------------
// Head: BN3 affine + avgpool(2x2) + fc(128->1) + sigmoid.
// ---------------------------------------------------------------------------
__global__ void head_kernel(const float* __restrict__ act4,
                            const float* __restrict__ s,
                            const float* __restrict__ t,
                            const float* __restrict__ fcw,
                            const float* __restrict__ fcb,
                            float* __restrict__ out) {
    int b = blockIdx.x;
    int c = threadIdx.x;  // 128 threads
    const float* p = act4 + b * 4 * 128;
    float mval = 0.25f * (p[c] + p[128 + c] + p[256 + c] + p[384 + c]);
    float v = (s[c] * mval + t[c]) * fcw[c];
    __shared__ float sh[128];
    sh[c] = v;
    __syncthreads();
    for (int o = 64; o > 0; o >>= 1) {
        if (c < o) sh[c] += sh[c + o];
        __syncthreads();
    }
    if (c == 0) {
        float zv = sh[0] + fcb[0];
        out[b] = 1.0f / (1.0f + expf(-zv));
    }
}

// ---------------------------------------------------------------------------
// Launch
// ---------------------------------------------------------------------------
extern "C" void kernel_launch(void* const* d_in, const int* in_sizes, int n_in,
                              void* d_out, int out_size) {
    const float* x   = (const float*)d_in[0];
    const float* bw1 = (const float*)d_in[1];
    const float* sw1 = (const float*)d_in[2];
    const float* sc1 = (const float*)d_in[3];
    const float* bw2 = (const float*)d_in[4];
    const float* sw2 = (const float*)d_in[5];
    const float* sc2 = (const float*)d_in[6];
    const float* bw3 = (const float*)d_in[7];
    const float* sw3 = (const float*)d_in[8];
    const float* sc3 = (const float*)d_in[9];
    const float* bw4 = (const float*)d_in[10];
    const float* sw4 = (const float*)d_in[11];
    const float* sc4 = (const float*)d_in[12];
    const float* g1  = (const float*)d_in[13];
    const float* b1  = (const float*)d_in[14];
    const float* g2  = (const float*)d_in[15];
    const float* b2  = (const float*)d_in[16];
    const float* g3  = (const float*)d_in[17];
    const float* b3  = (const float*)d_in[18];
    const float* fcw = (const float*)d_in[19];
    const float* fcb = (const float*)d_in[20];
    float* out = (float*)d_out;

    float *W, *act1, *act2, *act3, *act4, *part;
    float *s1, *t1, *s2, *t2, *s3, *t3;
    cudaGetSymbolAddress((void**)&W, g_W);
    cudaGetSymbolAddress((void**)&act1, g_act1);
    cudaGetSymbolAddress((void**)&act2, g_act2);
    cudaGetSymbolAddress((void**)&act3, g_act3);
    cudaGetSymbolAddress((void**)&act4, g_act4);
    cudaGetSymbolAddress((void**)&part, g_part);
    cudaGetSymbolAddress((void**)&s1, g_bnS1);
    cudaGetSymbolAddress((void**)&t1, g_bnT1);
    cudaGetSymbolAddress((void**)&s2, g_bnS2);
    cudaGetSymbolAddress((void**)&t2, g_bnT2);
    cudaGetSymbolAddress((void**)&s3, g_bnS3);
    cudaGetSymbolAddress((void**)&t3, g_bnT3);

    // ---- Layer 1: (512,3,32,32) NCHW -> (512,16,16,32) NHWC ----------------
    {
        const int F = 48, O = 32, M = 512 * 16 * 16;
        build_w_kernel<<<(6 * F * O + 255) / 256, 256>>>(bw1, sw1, sc1, W, F, O);
        kan_gemm_kernel<128, 32, 8><<<dim3(M / 128, 1, 1), 128>>>(
            x, W, act1, nullptr, nullptr, M, O, 3, 32, 4, 1, F);
    }
    // ---- Layer 2: -> (512,8,8,64) via feature-split2, BN1 stats ------------
    {
        const int F = 512, O = 64, M = 512 * 8 * 8;
        const int SPLIT = 2;
        build_w_kernel<<<(6 * F * O + 255) / 256, 256>>>(bw2, sw2, sc2, W, F, O);
        kan_gemm_kernel<128, 64, 8><<<dim3(M / 128, 1, SPLIT), 256>>>(
            act1, W, part, nullptr, nullptr, M, O, 32, 16, 3, 0, F / SPLIT);
        reduce_splitk_kernel<<<(M * O + 255) / 256, 256>>>(part, act2, M * O, SPLIT);
        bnstats_kernel<<<64, 256>>>(act2, g1, b1, s1, t1, 512 * 64, 64);
    }
    // ---- Layer 3: BN1 fused -> (512,4,4,128) via split2, BN2 stats ---------
    {
        const int F = 1024, O = 128, M = 512 * 4 * 4;
        const int SPLIT = 2;
        build_w_kernel<<<(6 * F * O + 255) / 256, 256>>>(bw3, sw3, sc3, W, F, O);
        kan_gemm_kernel<128, 64, 8><<<dim3(M / 128, O / 64, SPLIT), 256>>>(
            act2, W, part, s1, t1, M, O, 64, 8, 2, 0, F / SPLIT);
        reduce_splitk_kernel<<<(M * O + 255) / 256, 256>>>(part, act3, M * O, SPLIT);
        bnstats_kernel<<<128, 256>>>(act3, g2, b2, s2, t2, 512 * 16, 128);
    }
    // ---- Layer 4: BN2 fused -> (512,2,2,128) via split4, BN3 stats ---------
    {
        const int F = 2048, O = 128, M = 512 * 2 * 2;
        const int SPLIT = 4;
        build_w_kernel<<<(6 * F * O + 255) / 256, 256>>>(bw4, sw4, sc4, W, F, O);
        kan_gemm_kernel<64, 64, 8><<<dim3(M / 64, O / 64, SPLIT), 128>>>(
            act3, W, part, s2, t2, M, O, 128, 4, 1, 0, F / SPLIT);
        reduce_splitk_kernel<<<(M * O + 255) / 256, 256>>>(part, act4, M * O, SPLIT);
        bnstats_kernel<<<128, 256>>>(act4, g3, b3, s3, t3, 512 * 4, 128);
    }
    // ---- Head: BN3 + avgpool + fc + sigmoid --------------------------------
    head_kernel<<<512, 128>>>(act4, s3, t3, fcw, fcb, out);
}

// round 6
// speedup vs baseline: 1.5495x; 1.4346x over previous
#include <cuda_runtime.h>
#include <cuda_bf16.h>
#include <math.h>
#include <stdint.h>

// ---------------------------------------------------------------------------
// Scratch (device globals; allocation-free). ~25 MB total.
// ---------------------------------------------------------------------------
__device__ __align__(16) __nv_bfloat16 g_Whi[2097152];  // [O][Kpad] hi, max 128x16384
__device__ __align__(16) __nv_bfloat16 g_Wlo[2097152];  // [O][Kpad] lo
__device__ float g_act1[4194304];     // (512,16,16,32) NHWC
__device__ float g_act2[2097152];     // (512,8,8,64)   NHWC
__device__ float g_act3[1048576];     // (512,4,4,128)  NHWC
__device__ float g_act4[262144];      // (512,2,2,128)  NHWC
__device__ float g_part[2097152];     // split-K partials (max: L3, 2 x 8192 x 128)
__device__ float g_bnS1[64],  g_bnT1[64];
__device__ float g_bnS2[128], g_bnT2[128];
__device__ float g_bnS3[128], g_bnT3[128];

// ---------------------------------------------------------------------------
// Helpers
// ---------------------------------------------------------------------------
__device__ __forceinline__ uint32_t smem_u32(const void* p) {
    uint32_t a;
    asm("{ .reg .u64 t; cvta.to.shared.u64 t, %1; cvt.u32.u64 %0, t; }"
        : "=r"(a) : "l"(p));
    return a;
}
__device__ __forceinline__ uint32_t sw128(uint32_t off) {
    return off ^ ((off >> 3) & 0x70);
}
__device__ __forceinline__ void sts128(uint32_t addr, uint32_t a, uint32_t b,
                                       uint32_t c, uint32_t d) {
    asm volatile("st.shared.v4.b32 [%0], {%1, %2, %3, %4};"
                 :: "r"(addr), "r"(a), "r"(b), "r"(c), "r"(d) : "memory");
}
__device__ __forceinline__ void ldsm_x4(uint32_t* r, uint32_t addr) {
    asm volatile("ldmatrix.sync.aligned.m8n8.x4.shared.b16 {%0,%1,%2,%3}, [%4];"
                 : "=r"(r[0]), "=r"(r[1]), "=r"(r[2]), "=r"(r[3]) : "r"(addr));
}
__device__ __forceinline__ void mma16816(float* c, const uint32_t* a, const uint32_t* b) {
    asm volatile(
        "mma.sync.aligned.m16n8k16.row.col.f32.bf16.bf16.f32 "
        "{%0,%1,%2,%3}, {%4,%5,%6,%7}, {%8,%9}, {%0,%1,%2,%3};"
        : "+f"(c[0]), "+f"(c[1]), "+f"(c[2]), "+f"(c[3])
        : "r"(a[0]), "r"(a[1]), "r"(a[2]), "r"(a[3]), "r"(b[0]), "r"(b[1]));
}

// bf16 round-to-nearest-even
__device__ __forceinline__ uint16_t bf16r(float v) {
    uint32_t u = __float_as_uint(v);
    u += 0x7FFF + ((u >> 16) & 1);
    return (uint16_t)(u >> 16);
}
__device__ __forceinline__ float bf16f(uint16_t b) {
    return __uint_as_float(((uint32_t)b) << 16);
}

// ---------------------------------------------------------------------------
// Quadratic B-spline bases (grid_size=3, order=2) -> 5 bases; mirrors reference.
// ---------------------------------------------------------------------------
__device__ __forceinline__ void spline5(float x, float* bo) {
    float g[8];
#pragma unroll
    for (int i = 0; i < 8; i++) g[i] = (float)(i - 2) * (2.0f / 3.0f) - 1.0f;
    float b0[7];
#pragma unroll
    for (int j = 0; j < 7; j++) b0[j] = (x >= g[j] && x < g[j + 1]) ? 1.0f : 0.0f;
    float b1[6];
#pragma unroll
    for (int j = 0; j < 6; j++)
        b1[j] = (x - g[j]) * (1.0f / (g[j + 1] - g[j])) * b0[j]
              + (g[j + 2] - x) * (1.0f / (g[j + 2] - g[j + 1])) * b0[j + 1];
#pragma unroll
    for (int j = 0; j < 5; j++)
        bo[j] = (x - g[j]) * (1.0f / (g[j + 2] - g[j])) * b1[j]
              + (g[j + 3] - x) * (1.0f / (g[j + 3] - g[j + 1])) * b1[j + 1];
}

// ---------------------------------------------------------------------------
// Build split weights: Whi/Wlo[o][k], k = f*8 + t; t=0 base w, t=1..5 spline
// w * scaler, t=6,7 zero pad.
// ---------------------------------------------------------------------------
__global__ void build_wsplit_kernel(const float* __restrict__ bw,
                                    const float* __restrict__ sw,
                                    const float* __restrict__ sc,
                                    __nv_bfloat16* __restrict__ whi,
                                    __nv_bfloat16* __restrict__ wlo,
                                    int F, int O, int Kpad) {
    int idx = blockIdx.x * blockDim.x + threadIdx.x;
    if (idx >= O * Kpad) return;
    int o = idx / Kpad;
    int k = idx % Kpad;
    int f = k >> 3;
    int t = k & 7;
    float val = 0.0f;
    if (t == 0)      val = bw[o * F + f];
    else if (t <= 5) val = sw[(o * F + f) * 5 + (t - 1)] * sc[o * F + f];
    uint16_t hb = bf16r(val);
    float lo = val - bf16f(hb);
    uint16_t lb = bf16r(lo);
    *(uint16_t*)&whi[idx] = hb;
    *(uint16_t*)&wlo[idx] = lb;
}

// ---------------------------------------------------------------------------
// Fused KAN-conv GEMM on mma.sync tensor cores (bf16 hi/lo 3-term split,
// fp32 accum in registers). BM=128 x BN per block, 8 warps (4M x 2N).
// Per 64-value K chunk: gather+expand into SW128 smem (hi/lo), B copied from
// prebuilt global, then per warp ldmatrix + m16n8k16 MMAs.
// grid.z splits the feature range; block z writes C + z*M*O.
// ---------------------------------------------------------------------------
template <int BN>
__global__ __launch_bounds__(256)
void kan_mma_kernel(const float* __restrict__ src,
                    const __nv_bfloat16* __restrict__ Whi,
                    const __nv_bfloat16* __restrict__ Wlo,
                    float* __restrict__ C,
                    const float* __restrict__ bns,
                    const float* __restrict__ bnt,
                    int M, int O, int Cin, int Hin, int hs, int nchw,
                    int fCount, int Kpad) {
    constexpr int BM = 128;
    constexpr int BF = 8;                 // features per chunk -> 64 bf16 k
    constexpr int WN = BN / 2;            // warp N tile (32 or 16)
    constexpr int NA = WN / 8;            // N atoms per warp (4 or 2)
    constexpr int NPAIR = NA / 2;         // ldmatrix x4 covers 2 atoms (b0+b1 each)
    constexpr int A_BYTES = BM * 128;     // 16 KB per term tile
    constexpr int B_BYTES = BN * 128;     // 8 or 4 KB

    extern __shared__ char dynsmem[];
    uintptr_t tbase = ((uintptr_t)dynsmem + 1023) & ~(uintptr_t)1023;
    const uint32_t AHI = smem_u32((void*)tbase);
    const uint32_t ALO = AHI + A_BYTES;
    const uint32_t BHI = ALO + A_BYTES;
    const uint32_t BLO = BHI + B_BYTES;

    const int tid = threadIdx.x;
    const int lane = tid & 31;
    const int wid = tid >> 5;
    const int warp_m = wid & 3;           // 4 warps along M
    const int warp_n = wid >> 2;          // 2 warps along N

    const int z = blockIdx.z;
    const int fBase = z * fCount;
    const int row0 = blockIdx.x * BM;
    const int col0 = blockIdx.y * BN;
    float* Cz = C + z * M * O;

    float acc[2][NA][4];
#pragma unroll
    for (int i = 0; i < 2; i++)
#pragma unroll
        for (int j = 0; j < NA; j++)
#pragma unroll
            for (int q = 0; q < 4; q++) acc[i][j][q] = 0.0f;

    const int Hout = 1 << hs;
    const int hwMask = (Hout * Hout) - 1;
    const int hwShift = 2 * hs;
    const int NC = fCount / BF;

    // ldmatrix lane offsets (within-tile byte offsets, pre-swizzle)
    // A (row-major [m][k]): lanes 0-15 -> rows 0-15 @k0-7; 16-31 -> rows @+16B
    const uint32_t aRowOff = (uint32_t)(lane & 15) * 128 + ((uint32_t)(lane >> 4) << 4);
    // B (K-major [n][k], non-trans): lanes 0-7 n0-7/k0-7, 8-15 n0-7/k8-15,
    // 16-23 n8-15/k0-7, 24-31 n8-15/k8-15  => regs {b0,b1} for 2 n-atoms
    const uint32_t bRowOff = ((uint32_t)((lane & 7) + ((lane >> 4) << 3))) * 128 +
                             (((uint32_t)(lane >> 3) & 1u) << 4);

    for (int cch = 0; cch < NC; cch++) {
        // ---- A: gather + BN affine + relu/spline, bf16 hi/lo, swizzled ----
#pragma unroll
        for (int l = tid; l < BM * BF; l += 256) {
            const int mLocal = l & (BM - 1);
            const int fl = l >> 7;
            const int m = row0 + mLocal;
            const int f = fBase + cch * BF + fl;
            const int p = m & hwMask;
            const int b = m >> hwShift;
            const int ho = p >> hs, wo = p & (Hout - 1);
            const int c = f >> 4;
            const int r = f & 15;
            const int ih = 2 * ho + (r >> 2) - 1;
            const int iw = 2 * wo + (r & 3) - 1;
            float v = 0.0f;
            if ((unsigned)ih < (unsigned)Hin && (unsigned)iw < (unsigned)Hin) {
                int off = nchw
                    ? (((b * Cin + c) * Hin + ih) * Hin + iw)
                    : (((b * Hin + ih) * Hin + iw) * Cin + c);
                v = src[off];
                if (bns) v = fmaf(v, bns[c], bnt[c]);
            }
            float vals[8];
            vals[0] = fmaxf(v, 0.0f);
            spline5(v, &vals[1]);
            vals[6] = 0.0f; vals[7] = 0.0f;
            uint16_t hb[8], lb[8];
#pragma unroll
            for (int t = 0; t < 8; t++) {
                hb[t] = bf16r(vals[t]);
                lb[t] = bf16r(vals[t] - bf16f(hb[t]));
            }
            const uint32_t sw = sw128((uint32_t)(mLocal * 128 + fl * 16));
            sts128(AHI + sw,
                   (uint32_t)hb[0] | ((uint32_t)hb[1] << 16),
                   (uint32_t)hb[2] | ((uint32_t)hb[3] << 16),
                   (uint32_t)hb[4] | ((uint32_t)hb[5] << 16),
                   (uint32_t)hb[6] | ((uint32_t)hb[7] << 16));
            sts128(ALO + sw,
                   (uint32_t)lb[0] | ((uint32_t)lb[1] << 16),
                   (uint32_t)lb[2] | ((uint32_t)lb[3] << 16),
                   (uint32_t)lb[4] | ((uint32_t)lb[5] << 16),
                   (uint32_t)lb[6] | ((uint32_t)lb[7] << 16));
        }
        // ---- B: copy BN rows x 64 bf16 (hi & lo), swizzled ----
        {
            const int kG = (fBase + cch * BF) * 8;
#pragma unroll
            for (int l = tid; l < BN * 8; l += 256) {
                const int rown = l >> 3;
                const int cg = l & 7;
                const int gidx = (col0 + rown) * Kpad + kG + cg * 8;
                uint4 vh = *(const uint4*)&Whi[gidx];
                uint4 vl = *(const uint4*)&Wlo[gidx];
                const uint32_t sw = sw128((uint32_t)(rown * 128 + cg * 16));
                sts128(BHI + sw, vh.x, vh.y, vh.z, vh.w);
                sts128(BLO + sw, vl.x, vl.y, vl.z, vl.w);
            }
        }
        __syncthreads();

        // ---- compute: 4 K16 steps; 3-term split MMAs ----
#pragma unroll
        for (int ks = 0; ks < 4; ks++) {
            const uint32_t kb = (uint32_t)(ks * 32);  // bytes
            uint32_t ah[2][4], al[2][4];
#pragma unroll
            for (int am = 0; am < 2; am++) {
                const uint32_t off =
                    sw128((uint32_t)((warp_m * 32 + am * 16) * 128) + aRowOff + kb);
                ldsm_x4(ah[am], AHI + off);
                ldsm_x4(al[am], ALO + off);
            }
            uint32_t bh[NA][2], bl[NA][2];
#pragma unroll
            for (int pr = 0; pr < NPAIR; pr++) {
                const uint32_t off =
                    sw128((uint32_t)((warp_n * WN + pr * 16) * 128) + bRowOff + kb);
                uint32_t t[4];
                ldsm_x4(t, BHI + off);   // non-trans: [n][k] layout matches B frag
                bh[2 * pr][0] = t[0]; bh[2 * pr][1] = t[1];
                bh[2 * pr + 1][0] = t[2]; bh[2 * pr + 1][1] = t[3];
                ldsm_x4(t, BLO + off);
                bl[2 * pr][0] = t[0]; bl[2 * pr][1] = t[1];
                bl[2 * pr + 1][0] = t[2]; bl[2 * pr + 1][1] = t[3];
            }
#pragma unroll
            for (int am = 0; am < 2; am++)
#pragma unroll
                for (int an = 0; an < NA; an++) {
                    mma16816(acc[am][an], ah[am], bh[an]);
                    mma16816(acc[am][an], ah[am], bl[an]);
                    mma16816(acc[am][an], al[am], bh[an]);
                }
        }
        __syncthreads();
    }

    // ---- epilogue: write fragments ----
#pragma unroll
    for (int am = 0; am < 2; am++) {
        const int rr = row0 + warp_m * 32 + am * 16 + (lane >> 2);
#pragma unroll
        for (int an = 0; an < NA; an++) {
            const int cc = col0 + warp_n * WN + an * 8 + (lane & 3) * 2;
            *(float2*)&Cz[rr * O + cc] = make_float2(acc[am][an][0], acc[am][an][1]);
            *(float2*)&Cz[(rr + 8) * O + cc] = make_float2(acc[am][an][2], acc[am][an][3]);
        }
    }
}

// ---------------------------------------------------------------------------
// Split-K reduce (deterministic)
// ---------------------------------------------------------------------------
__global__ void reduce_splitk_kernel(const float* __restrict__ part,
                                     float* __restrict__ out, int MN, int S) {
    int idx = blockIdx.x * blockDim.x + threadIdx.x;
    if (idx >= MN) return;
    float a = 0.0f;
    for (int s = 0; s < S; s++) a += part[s * MN + idx];
    out[idx] = a;
}

// ---------------------------------------------------------------------------
// BN statistics -> fused affine y = x*s + t (double accum, deterministic).
// ---------------------------------------------------------------------------
__global__ void bnstats_kernel(const float* __restrict__ act,
                               const float* __restrict__ gamma,
                               const float* __restrict__ beta,
                               float* __restrict__ s_out,
                               float* __restrict__ t_out, int n, int C) {
    int c = blockIdx.x;
    double sum = 0.0, sum2 = 0.0;
    for (int e = threadIdx.x; e < n; e += blockDim.x) {
        float v = act[e * C + c];
        sum += v;
        sum2 += (double)v * v;
    }
    __shared__ double shs[256];
    __shared__ double sh2[256];
    shs[threadIdx.x] = sum;
    sh2[threadIdx.x] = sum2;
    __syncthreads();
    for (int o = 128; o > 0; o >>= 1) {
        if (threadIdx.x < o) {
            shs[threadIdx.x] += shs[threadIdx.x + o];
            sh2[threadIdx.x] += sh2[threadIdx.x + o];
        }
        __syncthreads();
    }
    if (threadIdx.x == 0) {
        double mean = shs[0] / n;
        double var = sh2[0] / n - mean * mean;
        double sv = (double)gamma[c] * rsqrt(var + 1e-5);
        s_out[c] = (float)sv;
        t_out[c] = (float)((double)beta[c] - mean * sv);
    }
}

// ---------------------------------------------------------------------------
// Head: BN3 affine + avgpool(2x2) + fc(128->1) + sigmoid.
// ---------------------------------------------------------------------------
__global__ void head_kernel(const float* __restrict__ act4,
                            const float* __restrict__ s,
                            const float* __restrict__ t,
                            const float* __restrict__ fcw,
                            const float* __restrict__ fcb,
                            float* __restrict__ out) {
    int b = blockIdx.x;
    int c = threadIdx.x;  // 128 threads
    const float* p = act4 + b * 4 * 128;
    float mval = 0.25f * (p[c] + p[128 + c] + p[256 + c] + p[384 + c]);
    float v = (s[c] * mval + t[c]) * fcw[c];
    __shared__ float sh[128];
    sh[c] = v;
    __syncthreads();
    for (int o = 64; o > 0; o >>= 1) {
        if (c < o) sh[c] += sh[c + o];
        __syncthreads();
    }
    if (c == 0) {
        float zv = sh[0] + fcb[0];
        out[b] = 1.0f / (1.0f + expf(-zv));
    }
}

// ---------------------------------------------------------------------------
// Launch
// ---------------------------------------------------------------------------
extern "C" void kernel_launch(void* const* d_in, const int* in_sizes, int n_in,
                              void* d_out, int out_size) {
    const float* x   = (const float*)d_in[0];
    const float* bw1 = (const float*)d_in[1];
    const float* sw1 = (const float*)d_in[2];
    const float* sc1 = (const float*)d_in[3];
    const float* bw2 = (const float*)d_in[4];
    const float* sw2 = (const float*)d_in[5];
    const float* sc2 = (const float*)d_in[6];
    const float* bw3 = (const float*)d_in[7];
    const float* sw3 = (const float*)d_in[8];
    const float* sc3 = (const float*)d_in[9];
    const float* bw4 = (const float*)d_in[10];
    const float* sw4 = (const float*)d_in[11];
    const float* sc4 = (const float*)d_in[12];
    const float* g1  = (const float*)d_in[13];
    const float* b1  = (const float*)d_in[14];
    const float* g2  = (const float*)d_in[15];
    const float* b2  = (const float*)d_in[16];
    const float* g3  = (const float*)d_in[17];
    const float* b3  = (const float*)d_in[18];
    const float* fcw = (const float*)d_in[19];
    const float* fcb = (const float*)d_in[20];
    float* out = (float*)d_out;

    __nv_bfloat16 *whi, *wlo;
    float *act1, *act2, *act3, *act4, *part;
    float *s1, *t1, *s2, *t2, *s3, *t3;
    cudaGetSymbolAddress((void**)&whi, g_Whi);
    cudaGetSymbolAddress((void**)&wlo, g_Wlo);
    cudaGetSymbolAddress((void**)&act1, g_act1);
    cudaGetSymbolAddress((void**)&act2, g_act2);
    cudaGetSymbolAddress((void**)&act3, g_act3);
    cudaGetSymbolAddress((void**)&act4, g_act4);
    cudaGetSymbolAddress((void**)&part, g_part);
    cudaGetSymbolAddress((void**)&s1, g_bnS1);
    cudaGetSymbolAddress((void**)&t1, g_bnT1);
    cudaGetSymbolAddress((void**)&s2, g_bnS2);
    cudaGetSymbolAddress((void**)&t2, g_bnT2);
    cudaGetSymbolAddress((void**)&s3, g_bnS3);
    cudaGetSymbolAddress((void**)&t3, g_bnT3);

    const int SMEM_DYN = 2 * 16384 + 2 * 8192 + 1024;  // A hi/lo + B hi/lo + align
    cudaFuncSetAttribute(kan_mma_kernel<32>,
                         cudaFuncAttributeMaxDynamicSharedMemorySize, SMEM_DYN);
    cudaFuncSetAttribute(kan_mma_kernel<64>,
                         cudaFuncAttributeMaxDynamicSharedMemorySize, SMEM_DYN);

    // ---- Layer 1: (512,3,32,32) NCHW -> (512,16,16,32) NHWC ----------------
    {
        const int F = 48, O = 32, M = 512 * 16 * 16, Kpad = 8 * F;
        build_wsplit_kernel<<<(O * Kpad + 255) / 256, 256>>>(bw1, sw1, sc1, whi, wlo, F, O, Kpad);
        kan_mma_kernel<32><<<dim3(M / 128, 1, 1), 256, SMEM_DYN>>>(
            x, whi, wlo, act1, nullptr, nullptr, M, O, 3, 32, 4, 1, F, Kpad);
    }
    // ---- Layer 2: -> (512,8,8,64), BN1 stats -------------------------------
    {
        const int F = 512, O = 64, M = 512 * 8 * 8, Kpad = 8 * F;
        build_wsplit_kernel<<<(O * Kpad + 255) / 256, 256>>>(bw2, sw2, sc2, whi, wlo, F, O, Kpad);
        kan_mma_kernel<64><<<dim3(M / 128, 1, 1), 256, SMEM_DYN>>>(
            act1, whi, wlo, act2, nullptr, nullptr, M, O, 32, 16, 3, 0, F, Kpad);
        bnstats_kernel<<<64, 256>>>(act2, g1, b1, s1, t1, 512 * 64, 64);
    }
    // ---- Layer 3: BN1 fused -> (512,4,4,128) via feature-split2, BN2 -------
    {
        const int F = 1024, O = 128, M = 512 * 4 * 4, Kpad = 8 * F;
        const int SPLIT = 2;
        build_wsplit_kernel<<<(O * Kpad + 255) / 256, 256>>>(bw3, sw3, sc3, whi, wlo, F, O, Kpad);
        kan_mma_kernel<64><<<dim3(M / 128, O / 64, SPLIT), 256, SMEM_DYN>>>(
            act2, whi, wlo, part, s1, t1, M, O, 64, 8, 2, 0, F / SPLIT, Kpad);
        reduce_splitk_kernel<<<(M * O + 255) / 256, 256>>>(part, act3, M * O, SPLIT);
        bnstats_kernel<<<128, 256>>>(act3, g2, b2, s2, t2, 512 * 16, 128);
    }
    // ---- Layer 4: BN2 fused -> (512,2,2,128) via feature-split4, BN3 -------
    {
        const int F = 2048, O = 128, M = 512 * 2 * 2, Kpad = 8 * F;
        const int SPLIT = 4;
        build_wsplit_kernel<<<(O * Kpad + 255) / 256, 256>>>(bw4, sw4, sc4, whi, wlo, F, O, Kpad);
        kan_mma_kernel<64><<<dim3(M / 128, O / 64, SPLIT), 256, SMEM_DYN>>>(
            act3, whi, wlo, part, s2, t2, M, O, 128, 4, 1, 0, F / SPLIT, Kpad);
        reduce_splitk_kernel<<<(M * O + 255) / 256, 256>>>(part, act4, M * O, SPLIT);
        bnstats_kernel<<<128, 256>>>(act4, g3, b3, s3, t3, 512 * 4, 128);
    }
    // ---- Head --------------------------------------------------------------
    head_kernel<<<512, 128>>>(act4, s3, t3, fcw, fcb, out);
}

// round 7
// speedup vs baseline: 2.1277x; 1.3731x over previous
#include <cuda_runtime.h>
#include <cuda_fp16.h>
#include <math.h>
#include <stdint.h>

// ---------------------------------------------------------------------------
// Scratch (device globals; allocation-free). ~42 MB total.
// ---------------------------------------------------------------------------
__device__ __align__(16) __half g_Whi[2097152];  // [O][Kpad] hi, max 128x16384
__device__ __align__(16) __half g_Wlo[2097152];  // [O][Kpad] lo
__device__ float g_act1[4194304];     // (512,16,16,32) NHWC
__device__ float g_act2[2097152];     // (512,8,8,64)   NHWC
__device__ float g_act3[1048576];     // (512,4,4,128)  NHWC
__device__ float g_act4[262144];      // (512,2,2,128)  NHWC
__device__ float g_part[4194304];     // split-K partials (max 16 MB)
__device__ float g_bnS1[64],  g_bnT1[64];
__device__ float g_bnS2[128], g_bnT2[128];
__device__ float g_bnS3[128], g_bnT3[128];

// ---------------------------------------------------------------------------
// Helpers
// ---------------------------------------------------------------------------
__device__ __forceinline__ uint32_t smem_u32(const void* p) {
    uint32_t a;
    asm("{ .reg .u64 t; cvta.to.shared.u64 t, %1; cvt.u32.u64 %0, t; }"
        : "=r"(a) : "l"(p));
    return a;
}
__device__ __forceinline__ uint32_t sw128(uint32_t off) {
    return off ^ ((off >> 3) & 0x70);
}
__device__ __forceinline__ void sts128(uint32_t addr, uint32_t a, uint32_t b,
                                       uint32_t c, uint32_t d) {
    asm volatile("st.shared.v4.b32 [%0], {%1, %2, %3, %4};"
                 :: "r"(addr), "r"(a), "r"(b), "r"(c), "r"(d) : "memory");
}
__device__ __forceinline__ void ldsm_x4(uint32_t* r, uint32_t addr) {
    asm volatile("ldmatrix.sync.aligned.m8n8.x4.shared.b16 {%0,%1,%2,%3}, [%4];"
                 : "=r"(r[0]), "=r"(r[1]), "=r"(r[2]), "=r"(r[3]) : "r"(addr));
}
__device__ __forceinline__ void mma16816(float* c, const uint32_t* a, const uint32_t* b) {
    asm volatile(
        "mma.sync.aligned.m16n8k16.row.col.f32.f16.f16.f32 "
        "{%0,%1,%2,%3}, {%4,%5,%6,%7}, {%8,%9}, {%0,%1,%2,%3};"
        : "+f"(c[0]), "+f"(c[1]), "+f"(c[2]), "+f"(c[3])
        : "r"(a[0]), "r"(a[1]), "r"(a[2]), "r"(a[3]), "r"(b[0]), "r"(b[1]));
}
__device__ __forceinline__ uint32_t h2pack(float a, float b) {
    __half2 h = __floats2half2_rn(a, b);
    return *reinterpret_cast<uint32_t*>(&h);
}

// ---------------------------------------------------------------------------
// Quadratic B-spline bases (grid_size=3, order=2) -> 5 bases; mirrors reference.
// ---------------------------------------------------------------------------
__device__ __forceinline__ void spline5(float x, float* bo) {
    float g[8];
#pragma unroll
    for (int i = 0; i < 8; i++) g[i] = (float)(i - 2) * (2.0f / 3.0f) - 1.0f;
    float b0[7];
#pragma unroll
    for (int j = 0; j < 7; j++) b0[j] = (x >= g[j] && x < g[j + 1]) ? 1.0f : 0.0f;
    float b1[6];
#pragma unroll
    for (int j = 0; j < 6; j++)
        b1[j] = (x - g[j]) * (1.0f / (g[j + 1] - g[j])) * b0[j]
              + (g[j + 2] - x) * (1.0f / (g[j + 2] - g[j + 1])) * b0[j + 1];
#pragma unroll
    for (int j = 0; j < 5; j++)
        bo[j] = (x - g[j]) * (1.0f / (g[j + 2] - g[j])) * b1[j]
              + (g[j + 3] - x) * (1.0f / (g[j + 3] - g[j + 1])) * b1[j + 1];
}

// ---------------------------------------------------------------------------
// Build split weights (fp16 hi/lo): W[o][k], k = f*8 + t; t=0 base w,
// t=1..5 spline w * scaler, t=6,7 zero pad.
// ---------------------------------------------------------------------------
__global__ void build_wsplit_kernel(const float* __restrict__ bw,
                                    const float* __restrict__ sw,
                                    const float* __restrict__ sc,
                                    __half* __restrict__ whi,
                                    __half* __restrict__ wlo,
                                    int F, int O, int Kpad) {
    int idx = blockIdx.x * blockDim.x + threadIdx.x;
    if (idx >= O * Kpad) return;
    int o = idx / Kpad;
    int k = idx % Kpad;
    int f = k >> 3;
    int t = k & 7;
    float val = 0.0f;
    if (t == 0)      val = bw[o * F + f];
    else if (t <= 5) val = sw[(o * F + f) * 5 + (t - 1)] * sc[o * F + f];
    __half h = __float2half_rn(val);
    __half l = __float2half_rn(val - __half2float(h));
    whi[idx] = h;
    wlo[idx] = l;
}

// ---------------------------------------------------------------------------
// Fused KAN-conv GEMM on mma.sync (fp16 A single-term, fp16 W hi/lo 2-term,
// fp32 accum). BM=128 x BN, 8 warps (4M x 2N). Double-buffered smem chunks
// with register prefetch of next chunk's gathers (overlaps MMA).
// grid.z splits the feature range; block z writes C + z*M*O.
// ---------------------------------------------------------------------------
template <int BN>
__global__ __launch_bounds__(256)
void kan_mma_kernel(const float* __restrict__ src,
                    const __half* __restrict__ Whi,
                    const __half* __restrict__ Wlo,
                    float* __restrict__ C,
                    const float* __restrict__ bns,
                    const float* __restrict__ bnt,
                    int M, int O, int Cin, int Hin, int hs, int nchw,
                    int fCount, int Kpad) {
    constexpr int BM = 128;
    constexpr int BF = 8;                  // features per chunk -> 64 fp16 k
    constexpr int WN = BN / 2;
    constexpr int NA = WN / 8;
    constexpr int NPAIR = NA / 2;
    constexpr int A_BYTES = BM * 128;      // 16 KB
    constexpr int B_BYTES = BN * 128;      // 8 or 4 KB
    constexpr int BUF_STRIDE = A_BYTES + 2 * B_BYTES;
    constexpr int BITER = (BN * 8) / 256;  // B sts128 pairs per thread (2 or 1)

    extern __shared__ char dynsmem[];
    uintptr_t tbase = ((uintptr_t)dynsmem + 1023) & ~(uintptr_t)1023;
    const uint32_t base0 = smem_u32((void*)tbase);

    const int tid = threadIdx.x;
    const int lane = tid & 31;
    const int wid = tid >> 5;
    const int warp_m = wid & 3;
    const int warp_n = wid >> 2;

    const int z = blockIdx.z;
    const int fBase = z * fCount;
    const int row0 = blockIdx.x * BM;
    const int col0 = blockIdx.y * BN;
    float* Cz = C + z * M * O;

    float acc[2][NA][4];
#pragma unroll
    for (int i = 0; i < 2; i++)
#pragma unroll
        for (int j = 0; j < NA; j++)
#pragma unroll
            for (int q = 0; q < 4; q++) acc[i][j][q] = 0.0f;

    const int Hout = 1 << hs;
    const int hwMask = (Hout * Hout) - 1;
    const int hwShift = 2 * hs;
    const int NC = fCount / BF;

    // ldmatrix lane offsets (within-tile byte offsets, pre-swizzle)
    const uint32_t aRowOff = (uint32_t)(lane & 15) * 128 + ((uint32_t)(lane >> 4) << 4);
    const uint32_t bRowOff = ((uint32_t)((lane & 7) + ((lane >> 4) << 3))) * 128 +
                             (((uint32_t)(lane >> 3) & 1u) << 4);

    float pv[4];
    uint4 pbh[BITER], pbl[BITER];

    auto prefetchA = [&](int cc) {
#pragma unroll
        for (int it = 0; it < 4; it++) {
            const int l = tid + it * 256;
            const int mLocal = l & (BM - 1);
            const int fl = l >> 7;
            const int m = row0 + mLocal;
            const int f = fBase + cc * BF + fl;
            const int p = m & hwMask;
            const int b = m >> hwShift;
            const int ho = p >> hs, wo = p & (Hout - 1);
            const int c = f >> 4;
            const int r = f & 15;
            const int ih = 2 * ho + (r >> 2) - 1;
            const int iw = 2 * wo + (r & 3) - 1;
            float v = 0.0f;
            if ((unsigned)ih < (unsigned)Hin && (unsigned)iw < (unsigned)Hin) {
                int off = nchw
                    ? (((b * Cin + c) * Hin + ih) * Hin + iw)
                    : (((b * Hin + ih) * Hin + iw) * Cin + c);
                v = src[off];
                if (bns) v = fmaf(v, bns[c], bnt[c]);
            }
            pv[it] = v;
        }
    };
    auto prefetchB = [&](int cc) {
        const int kG = (fBase + cc * BF) * 8;
#pragma unroll
        for (int it = 0; it < BITER; it++) {
            const int l = tid + it * 256;
            const int rown = l >> 3;
            const int cg = l & 7;
            const int gidx = (col0 + rown) * Kpad + kG + cg * 8;
            pbh[it] = *(const uint4*)&Whi[gidx];
            pbl[it] = *(const uint4*)&Wlo[gidx];
        }
    };

    prefetchA(0);
    prefetchB(0);

    for (int cch = 0; cch < NC; cch++) {
        const int buf = cch & 1;
        const uint32_t A0 = base0 + buf * BUF_STRIDE;
        const uint32_t BH0 = A0 + A_BYTES;
        const uint32_t BL0 = BH0 + B_BYTES;

        // ---- convert + store prefetched A ----
#pragma unroll
        for (int it = 0; it < 4; it++) {
            const int l = tid + it * 256;
            const int mLocal = l & (BM - 1);
            const int fl = l >> 7;
            const float v = pv[it];
            float vals[8];
            vals[0] = fmaxf(v, 0.0f);
            spline5(v, &vals[1]);
            const uint32_t sw = sw128((uint32_t)(mLocal * 128 + fl * 16));
            sts128(A0 + sw, h2pack(vals[0], vals[1]), h2pack(vals[2], vals[3]),
                   h2pack(vals[4], vals[5]), 0u);
        }
        // ---- store prefetched B ----
#pragma unroll
        for (int it = 0; it < BITER; it++) {
            const int l = tid + it * 256;
            const int rown = l >> 3;
            const int cg = l & 7;
            const uint32_t sw = sw128((uint32_t)(rown * 128 + cg * 16));
            sts128(BH0 + sw, pbh[it].x, pbh[it].y, pbh[it].z, pbh[it].w);
            sts128(BL0 + sw, pbl[it].x, pbl[it].y, pbl[it].z, pbl[it].w);
        }
        __syncthreads();

        // ---- prefetch next chunk (overlaps MMA below) ----
        if (cch + 1 < NC) {
            prefetchA(cch + 1);
            prefetchB(cch + 1);
        }

        // ---- MMA: 4 K16 steps, 2 split terms ----
#pragma unroll
        for (int ks = 0; ks < 4; ks++) {
            const uint32_t kb = (uint32_t)(ks * 32);
            uint32_t ah[2][4];
#pragma unroll
            for (int am = 0; am < 2; am++) {
                const uint32_t off =
                    sw128((uint32_t)((warp_m * 32 + am * 16) * 128) + aRowOff + kb);
                ldsm_x4(ah[am], A0 + off);
            }
            uint32_t bh[NA][2], bl[NA][2];
#pragma unroll
            for (int pr = 0; pr < NPAIR; pr++) {
                const uint32_t off =
                    sw128((uint32_t)((warp_n * WN + pr * 16) * 128) + bRowOff + kb);
                uint32_t t[4];
                ldsm_x4(t, BH0 + off);
                bh[2 * pr][0] = t[0]; bh[2 * pr][1] = t[1];
                bh[2 * pr + 1][0] = t[2]; bh[2 * pr + 1][1] = t[3];
                ldsm_x4(t, BL0 + off);
                bl[2 * pr][0] = t[0]; bl[2 * pr][1] = t[1];
                bl[2 * pr + 1][0] = t[2]; bl[2 * pr + 1][1] = t[3];
            }
#pragma unroll
            for (int am = 0; am < 2; am++)
#pragma unroll
                for (int an = 0; an < NA; an++) {
                    mma16816(acc[am][an], ah[am], bh[an]);
                    mma16816(acc[am][an], ah[am], bl[an]);
                }
        }
        // no trailing sync: next iteration writes the other buffer, and its
        // pre-MMA sync guarantees all readers of that buffer have finished.
    }

    // ---- epilogue: write fragments ----
#pragma unroll
    for (int am = 0; am < 2; am++) {
        const int rr = row0 + warp_m * 32 + am * 16 + (lane >> 2);
#pragma unroll
        for (int an = 0; an < NA; an++) {
            const int cc = col0 + warp_n * WN + an * 8 + (lane & 3) * 2;
            *(float2*)&Cz[rr * O + cc] = make_float2(acc[am][an][0], acc[am][an][1]);
            *(float2*)&Cz[(rr + 8) * O + cc] = make_float2(acc[am][an][2], acc[am][an][3]);
        }
    }
}

// ---------------------------------------------------------------------------
// Split-K reduce (deterministic)
// ---------------------------------------------------------------------------
__global__ void reduce_splitk_kernel(const float* __restrict__ part,
                                     float* __restrict__ out, int MN, int S) {
    int idx = blockIdx.x * blockDim.x + threadIdx.x;
    if (idx >= MN) return;
    float a = 0.0f;
    for (int s = 0; s < S; s++) a += part[s * MN + idx];
    out[idx] = a;
}

// ---------------------------------------------------------------------------
// BN statistics -> fused affine y = x*s + t (double accum, deterministic).
// ---------------------------------------------------------------------------
__global__ void bnstats_kernel(const float* __restrict__ act,
                               const float* __restrict__ gamma,
                               const float* __restrict__ beta,
                               float* __restrict__ s_out,
                               float* __restrict__ t_out, int n, int C) {
    int c = blockIdx.x;
    double sum = 0.0, sum2 = 0.0;
    for (int e = threadIdx.x; e < n; e += blockDim.x) {
        float v = act[e * C + c];
        sum += v;
        sum2 += (double)v * v;
    }
    __shared__ double shs[256];
    __shared__ double sh2[256];
    shs[threadIdx.x] = sum;
    sh2[threadIdx.x] = sum2;
    __syncthreads();
    for (int o = 128; o > 0; o >>= 1) {
        if (threadIdx.x < o) {
            shs[threadIdx.x] += shs[threadIdx.x + o];
            sh2[threadIdx.x] += sh2[threadIdx.x + o];
        }
        __syncthreads();
    }
    if (threadIdx.x == 0) {
        double mean = shs[0] / n;
        double var = sh2[0] / n - mean * mean;
        double sv = (double)gamma[c] * rsqrt(var + 1e-5);
        s_out[c] = (float)sv;
        t_out[c] = (float)((double)beta[c] - mean * sv);
    }
}

// ---------------------------------------------------------------------------
// Head: BN3 affine + avgpool(2x2) + fc(128->1) + sigmoid.
// ---------------------------------------------------------------------------
__global__ void head_kernel(const float* __restrict__ act4,
                            const float* __restrict__ s,
                            const float* __restrict__ t,
                            const float* __restrict__ fcw,
                            const float* __restrict__ fcb,
                            float* __restrict__ out) {
    int b = blockIdx.x;
    int c = threadIdx.x;  // 128 threads
    const float* p = act4 + b * 4 * 128;
    float mval = 0.25f * (p[c] + p[128 + c] + p[256 + c] + p[384 + c]);
    float v = (s[c] * mval + t[c]) * fcw[c];
    __shared__ float sh[128];
    sh[c] = v;
    __syncthreads();
    for (int o = 64; o > 0; o >>= 1) {
        if (c < o) sh[c] += sh[c + o];
        __syncthreads();
    }
    if (c == 0) {
        float zv = sh[0] + fcb[0];
        out[b] = 1.0f / (1.0f + expf(-zv));
    }
}

// ---------------------------------------------------------------------------
// Launch
// ---------------------------------------------------------------------------
extern "C" void kernel_launch(void* const* d_in, const int* in_sizes, int n_in,
                              void* d_out, int out_size) {
    const float* x   = (const float*)d_in[0];
    const float* bw1 = (const float*)d_in[1];
    const float* sw1 = (const float*)d_in[2];
    const float* sc1 = (const float*)d_in[3];
    const float* bw2 = (const float*)d_in[4];
    const float* sw2 = (const float*)d_in[5];
    const float* sc2 = (const float*)d_in[6];
    const float* bw3 = (const float*)d_in[7];
    const float* sw3 = (const float*)d_in[8];
    const float* sc3 = (const float*)d_in[9];
    const float* bw4 = (const float*)d_in[10];
    const float* sw4 = (const float*)d_in[11];
    const float* sc4 = (const float*)d_in[12];
    const float* g1  = (const float*)d_in[13];
    const float* b1  = (const float*)d_in[14];
    const float* g2  = (const float*)d_in[15];
    const float* b2  = (const float*)d_in[16];
    const float* g3  = (const float*)d_in[17];
    const float* b3  = (const float*)d_in[18];
    const float* fcw = (const float*)d_in[19];
    const float* fcb = (const float*)d_in[20];
    float* out = (float*)d_out;

    __half *whi, *wlo;
    float *act1, *act2, *act3, *act4, *part;
    float *s1, *t1, *s2, *t2, *s3, *t3;
    cudaGetSymbolAddress((void**)&whi, g_Whi);
    cudaGetSymbolAddress((void**)&wlo, g_Wlo);
    cudaGetSymbolAddress((void**)&act1, g_act1);
    cudaGetSymbolAddress((void**)&act2, g_act2);
    cudaGetSymbolAddress((void**)&act3, g_act3);
    cudaGetSymbolAddress((void**)&act4, g_act4);
    cudaGetSymbolAddress((void**)&part, g_part);
    cudaGetSymbolAddress((void**)&s1, g_bnS1);
    cudaGetSymbolAddress((void**)&t1, g_bnT1);
    cudaGetSymbolAddress((void**)&s2, g_bnS2);
    cudaGetSymbolAddress((void**)&t2, g_bnT2);
    cudaGetSymbolAddress((void**)&s3, g_bnS3);
    cudaGetSymbolAddress((void**)&t3, g_bnT3);

    const int SMEM64 = 2 * (16384 + 2 * 64 * 128) + 1024;  // 66560
    const int SMEM32 = 2 * (16384 + 2 * 32 * 128) + 1024;  // 50176
    cudaFuncSetAttribute(kan_mma_kernel<32>,
                         cudaFuncAttributeMaxDynamicSharedMemorySize, SMEM32);
    cudaFuncSetAttribute(kan_mma_kernel<64>,
                         cudaFuncAttributeMaxDynamicSharedMemorySize, SMEM64);

    // ---- Layer 1: (512,3,32,32) NCHW -> (512,16,16,32) NHWC ----------------
    {
        const int F = 48, O = 32, M = 512 * 16 * 16, Kpad = 8 * F;
        build_wsplit_kernel<<<(O * Kpad + 255) / 256, 256>>>(bw1, sw1, sc1, whi, wlo, F, O, Kpad);
        kan_mma_kernel<32><<<dim3(M / 128, 1, 1), 256, SMEM32>>>(
            x, whi, wlo, act1, nullptr, nullptr, M, O, 3, 32, 4, 1, F, Kpad);
    }
    // ---- Layer 2: -> (512,8,8,64) via split2, BN1 stats ---------------------
    {
        const int F = 512, O = 64, M = 512 * 8 * 8, Kpad = 8 * F;
        const int SPLIT = 2;
        build_wsplit_kernel<<<(O * Kpad + 255) / 256, 256>>>(bw2, sw2, sc2, whi, wlo, F, O, Kpad);
        kan_mma_kernel<64><<<dim3(M / 128, 1, SPLIT), 256, SMEM64>>>(
            act1, whi, wlo, part, nullptr, nullptr, M, O, 32, 16, 3, 0, F / SPLIT, Kpad);
        reduce_splitk_kernel<<<(M * O + 255) / 256, 256>>>(part, act2, M * O, SPLIT);
        bnstats_kernel<<<64, 256>>>(act2, g1, b1, s1, t1, 512 * 64, 64);
    }
    // ---- Layer 3: BN1 fused -> (512,4,4,128) via split4, BN2 stats ----------
    {
        const int F = 1024, O = 128, M = 512 * 4 * 4, Kpad = 8 * F;
        const int SPLIT = 4;
        build_wsplit_kernel<<<(O * Kpad + 255) / 256, 256>>>(bw3, sw3, sc3, whi, wlo, F, O, Kpad);
        kan_mma_kernel<64><<<dim3(M / 128, O / 64, SPLIT), 256, SMEM64>>>(
            act2, whi, wlo, part, s1, t1, M, O, 64, 8, 2, 0, F / SPLIT, Kpad);
        reduce_splitk_kernel<<<(M * O + 255) / 256, 256>>>(part, act3, M * O, SPLIT);
        bnstats_kernel<<<128, 256>>>(act3, g2, b2, s2, t2, 512 * 16, 128);
    }
    // ---- Layer 4: BN2 fused -> (512,2,2,128) via split8, BN3 stats ----------
    {
        const int F = 2048, O = 128, M = 512 * 2 * 2, Kpad = 8 * F;
        const int SPLIT = 8;
        build_wsplit_kernel<<<(O * Kpad + 255) / 256, 256>>>(bw4, sw4, sc4, whi, wlo, F, O, Kpad);
        kan_mma_kernel<64><<<dim3(M / 128, O / 64, SPLIT), 256, SMEM64>>>(
            act3, whi, wlo, part, s2, t2, M, O, 128, 4, 1, 0, F / SPLIT, Kpad);
        reduce_splitk_kernel<<<(M * O + 255) / 256, 256>>>(part, act4, M * O, SPLIT);
        bnstats_kernel<<<128, 256>>>(act4, g3, b3, s3, t3, 512 * 4, 128);
    }
    // ---- Head --------------------------------------------------------------
    head_kernel<<<512, 128>>>(act4, s3, t3, fcw, fcb, out);
}